// round 8
// baseline (speedup 1.0000x reference)
#include <cuda_runtime.h>
#include <cstdint>

// Problem constants
#define B_  4
#define S_  2048
#define D_  1024
#define H_  16
#define HD_ 64
#define M_  (B_*S_)   // 8192 rows

// Scratch (device globals — no allocation allowed)
__device__ float g_q[B_*H_*S_*HD_];   // [B,H,S,HD]
__device__ float g_k[B_*H_*S_*HD_];
__device__ float g_v[B_*H_*S_*HD_];
__device__ float g_ctx[(size_t)B_*S_*D_]; // [B,S,D]

// ---------------------------------------------------------------------------
// GEMM tile config: C[M,N] = A[M,K] * W[N,K]^T  (both K-major, row-major)
// 128x128 block tile, BK=16, 256 threads, 8x8 per-thread microtile with
// strided mapping (row = tm+16*i, col = tn+16*j) for conflict-free LDS.
// ---------------------------------------------------------------------------
#define BM 128
#define BN 128
#define BK 16

// Fused QKV projection: blockIdx.z in {0,1,2} selects (Wq->g_q, Wk->g_k, Wv->g_v).
// Epilogue permutes [m=b*S+s, n=h*HD+hd] -> [B,H,S,HD].
__global__ __launch_bounds__(256) void qkv_proj_kernel(
    const float* __restrict__ x,
    const float* __restrict__ Wq,
    const float* __restrict__ Wk,
    const float* __restrict__ Wv)
{
    const float* W   = (blockIdx.z == 0) ? Wq : (blockIdx.z == 1) ? Wk : Wv;
    float*       dst = (blockIdx.z == 0) ? g_q : (blockIdx.z == 1) ? g_k : g_v;

    __shared__ float As[BK][BM + 1];
    __shared__ float Bs[BK][BN + 1];

    const int tid = threadIdx.x;
    const int tm  = tid >> 4;   // 0..15
    const int tn  = tid & 15;   // 0..15
    const int m0  = blockIdx.y * BM;
    const int n0  = blockIdx.x * BN;

    float acc[8][8];
#pragma unroll
    for (int i = 0; i < 8; ++i)
#pragma unroll
        for (int j = 0; j < 8; ++j) acc[i][j] = 0.0f;

    for (int k0 = 0; k0 < D_; k0 += BK) {
#pragma unroll
        for (int l = 0; l < 2; ++l) {
            int idx = tid + l * 256;          // 0..511
            int r   = idx >> 2;               // 0..127
            int c4  = (idx & 3) << 2;         // 0,4,8,12
            float4 va = *(const float4*)(x + (size_t)(m0 + r) * D_ + k0 + c4);
            As[c4 + 0][r] = va.x; As[c4 + 1][r] = va.y;
            As[c4 + 2][r] = va.z; As[c4 + 3][r] = va.w;
            float4 vb = *(const float4*)(W + (size_t)(n0 + r) * D_ + k0 + c4);
            Bs[c4 + 0][r] = vb.x; Bs[c4 + 1][r] = vb.y;
            Bs[c4 + 2][r] = vb.z; Bs[c4 + 3][r] = vb.w;
        }
        __syncthreads();
#pragma unroll
        for (int k = 0; k < BK; ++k) {
            float a[8], b[8];
#pragma unroll
            for (int i = 0; i < 8; ++i) a[i] = As[k][tm + 16 * i];
#pragma unroll
            for (int j = 0; j < 8; ++j) b[j] = Bs[k][tn + 16 * j];
#pragma unroll
            for (int i = 0; i < 8; ++i)
#pragma unroll
                for (int j = 0; j < 8; ++j) acc[i][j] += a[i] * b[j];
        }
        __syncthreads();
    }

    // Permuted store: [B,H,S,HD]
#pragma unroll
    for (int i = 0; i < 8; ++i) {
        int m = m0 + tm + 16 * i;
        int b = m >> 11;            // / 2048
        int s = m & (S_ - 1);
#pragma unroll
        for (int j = 0; j < 8; ++j) {
            int n  = n0 + tn + 16 * j;
            int h  = n >> 6;
            int hd = n & 63;
            dst[(((size_t)(b * H_ + h)) * S_ + s) * HD_ + hd] = acc[i][j];
        }
    }
}

// Output projection: out[B,S,D] = ctx @ Wo^T (plain layout store)
__global__ __launch_bounds__(256) void oproj_kernel(
    const float* __restrict__ Wo,
    float* __restrict__ out)
{
    __shared__ float As[BK][BM + 1];
    __shared__ float Bs[BK][BN + 1];

    const int tid = threadIdx.x;
    const int tm  = tid >> 4;
    const int tn  = tid & 15;
    const int m0  = blockIdx.y * BM;
    const int n0  = blockIdx.x * BN;

    float acc[8][8];
#pragma unroll
    for (int i = 0; i < 8; ++i)
#pragma unroll
        for (int j = 0; j < 8; ++j) acc[i][j] = 0.0f;

    for (int k0 = 0; k0 < D_; k0 += BK) {
#pragma unroll
        for (int l = 0; l < 2; ++l) {
            int idx = tid + l * 256;
            int r   = idx >> 2;
            int c4  = (idx & 3) << 2;
            float4 va = *(const float4*)(g_ctx + (size_t)(m0 + r) * D_ + k0 + c4);
            As[c4 + 0][r] = va.x; As[c4 + 1][r] = va.y;
            As[c4 + 2][r] = va.z; As[c4 + 3][r] = va.w;
            float4 vb = *(const float4*)(Wo + (size_t)(n0 + r) * D_ + k0 + c4);
            Bs[c4 + 0][r] = vb.x; Bs[c4 + 1][r] = vb.y;
            Bs[c4 + 2][r] = vb.z; Bs[c4 + 3][r] = vb.w;
        }
        __syncthreads();
#pragma unroll
        for (int k = 0; k < BK; ++k) {
            float a[8], b[8];
#pragma unroll
            for (int i = 0; i < 8; ++i) a[i] = As[k][tm + 16 * i];
#pragma unroll
            for (int j = 0; j < 8; ++j) b[j] = Bs[k][tn + 16 * j];
#pragma unroll
            for (int i = 0; i < 8; ++i)
#pragma unroll
                for (int j = 0; j < 8; ++j) acc[i][j] += a[i] * b[j];
        }
        __syncthreads();
    }

#pragma unroll
    for (int i = 0; i < 8; ++i) {
        int m = m0 + tm + 16 * i;
#pragma unroll
        for (int j = 0; j < 8; ++j) {
            int n = n0 + tn + 16 * j;
            out[(size_t)m * D_ + n] = acc[i][j];
        }
    }
}

// ---------------------------------------------------------------------------
// Flash attention (fp32, causal). One block per (q-tile of 64 rows, b*h).
// 256 threads: ty=tid/16 owns rows {ty+16i}, tx=tid%16 owns cols {tx+16j}.
// smem: q_s[64][64], k_s[64][65] (reused for P), v_s[64][65]  -> 49664 B dyn.
// ---------------------------------------------------------------------------
#define QT 64
#define NEG_BIG (-1e30f)

__global__ __launch_bounds__(256) void attn_kernel()
{
    extern __shared__ float sm[];
    float* q_s = sm;                   // 64*64
    float* k_s = sm + 64 * 64;         // 64*65, reused as P
    float* v_s = k_s + 64 * 65;        // 64*65

    const int qt = blockIdx.x;         // 0..31
    const int bh = blockIdx.y;         // 0..63
    const float* Qg = g_q + (size_t)bh * S_ * HD_;
    const float* Kg = g_k + (size_t)bh * S_ * HD_;
    const float* Vg = g_v + (size_t)bh * S_ * HD_;

    const int tid = threadIdx.x;
    const int tx  = tid & 15;
    const int ty  = tid >> 4;

    // load Q tile (stride 64; reads are broadcast so no pad needed)
    for (int idx = tid; idx < QT * HD_; idx += 256) {
        int r = idx >> 6, c = idx & 63;
        q_s[r * 64 + c] = Qg[(size_t)(qt * QT + r) * HD_ + c];
    }

    float m_r[4], l_r[4], o[4][4];
#pragma unroll
    for (int i = 0; i < 4; ++i) {
        m_r[i] = NEG_BIG; l_r[i] = 0.0f;
#pragma unroll
        for (int j = 0; j < 4; ++j) o[i][j] = 0.0f;
    }

    for (int kt = 0; kt <= qt; ++kt) {
        __syncthreads();  // protect k_s (holds P of prev iter) + q_s on first iter
        for (int idx = tid; idx < QT * HD_; idx += 256) {
            int r = idx >> 6, c = idx & 63;
            k_s[r * 65 + c] = Kg[(size_t)(kt * QT + r) * HD_ + c];
            v_s[r * 65 + c] = Vg[(size_t)(kt * QT + r) * HD_ + c];
        }
        __syncthreads();

        // S = Q K^T  (each thread 4x4)
        float sv[4][4];
#pragma unroll
        for (int i = 0; i < 4; ++i)
#pragma unroll
            for (int j = 0; j < 4; ++j) sv[i][j] = 0.0f;

#pragma unroll 8
        for (int d = 0; d < HD_; ++d) {
            float qv[4], kv[4];
#pragma unroll
            for (int i = 0; i < 4; ++i) qv[i] = q_s[(ty + 16 * i) * 64 + d];
#pragma unroll
            for (int j = 0; j < 4; ++j) kv[j] = k_s[(tx + 16 * j) * 65 + d];
#pragma unroll
            for (int i = 0; i < 4; ++i)
#pragma unroll
                for (int j = 0; j < 4; ++j) sv[i][j] += qv[i] * kv[j];
        }

        const float sc = 0.125f;  // 1/sqrt(64)
        if (kt == qt) {
#pragma unroll
            for (int i = 0; i < 4; ++i)
#pragma unroll
                for (int j = 0; j < 4; ++j) {
                    int row = ty + 16 * i, col = tx + 16 * j;
                    sv[i][j] = (col > row) ? NEG_BIG : sv[i][j] * sc;
                }
        } else {
#pragma unroll
            for (int i = 0; i < 4; ++i)
#pragma unroll
                for (int j = 0; j < 4; ++j) sv[i][j] *= sc;
        }

        // row max across the 16 tx lanes (width-16 shfl segments)
        float mx[4];
#pragma unroll
        for (int i = 0; i < 4; ++i) {
            float v = fmaxf(fmaxf(sv[i][0], sv[i][1]), fmaxf(sv[i][2], sv[i][3]));
            mx[i] = v;
        }
#pragma unroll
        for (int off = 8; off; off >>= 1)
#pragma unroll
            for (int i = 0; i < 4; ++i)
                mx[i] = fmaxf(mx[i], __shfl_xor_sync(0xffffffffu, mx[i], off, 16));

        float al[4];
#pragma unroll
        for (int i = 0; i < 4; ++i) {
            float mn = fmaxf(m_r[i], mx[i]);
            al[i] = __expf(m_r[i] - mn);
            m_r[i] = mn;
        }

        float ps[4] = {0.f, 0.f, 0.f, 0.f};
#pragma unroll
        for (int i = 0; i < 4; ++i)
#pragma unroll
            for (int j = 0; j < 4; ++j) {
                float p = __expf(sv[i][j] - m_r[i]);
                sv[i][j] = p;
                ps[i] += p;
            }
#pragma unroll
        for (int off = 8; off; off >>= 1)
#pragma unroll
            for (int i = 0; i < 4; ++i)
                ps[i] += __shfl_xor_sync(0xffffffffu, ps[i], off, 16);

#pragma unroll
        for (int i = 0; i < 4; ++i) {
            l_r[i] = l_r[i] * al[i] + ps[i];
#pragma unroll
            for (int j = 0; j < 4; ++j) o[i][j] *= al[i];
        }

        __syncthreads();  // all threads done reading k_s -> safe to overwrite with P
#pragma unroll
        for (int i = 0; i < 4; ++i)
#pragma unroll
            for (int j = 0; j < 4; ++j)
                k_s[(ty + 16 * i) * 65 + (tx + 16 * j)] = sv[i][j];
        __syncthreads();

        // O += P V
#pragma unroll 8
        for (int k = 0; k < QT; ++k) {
            float pv[4], vv[4];
#pragma unroll
            for (int i = 0; i < 4; ++i) pv[i] = k_s[(ty + 16 * i) * 65 + k];
#pragma unroll
            for (int j = 0; j < 4; ++j) vv[j] = v_s[k * 65 + (tx + 16 * j)];
#pragma unroll
            for (int i = 0; i < 4; ++i)
#pragma unroll
                for (int j = 0; j < 4; ++j) o[i][j] += pv[i] * vv[j];
        }
    }

    // epilogue: ctx[b, s, h*64+c] = O / l
    const int b = bh >> 4;
    const int h = bh & 15;
#pragma unroll
    for (int i = 0; i < 4; ++i) {
        float inv = 1.0f / l_r[i];
        int srow = qt * QT + ty + 16 * i;
#pragma unroll
        for (int j = 0; j < 4; ++j) {
            int c = tx + 16 * j;
            g_ctx[((size_t)b * S_ + srow) * D_ + h * HD_ + c] = o[i][j] * inv;
        }
    }
}

// ---------------------------------------------------------------------------
// Launch
// ---------------------------------------------------------------------------
extern "C" void kernel_launch(void* const* d_in, const int* in_sizes, int n_in,
                              void* d_out, int out_size)
{
    const float* x  = (const float*)d_in[0];
    const float* Wq = (const float*)d_in[1];
    const float* Wk = (const float*)d_in[2];
    const float* Wv = (const float*)d_in[3];
    const float* Wo = (const float*)d_in[4];
    float* out = (float*)d_out;

    // 1) fused QKV projections (writes g_q/g_k/g_v in [B,H,S,HD])
    {
        dim3 grid(D_ / BN, M_ / BM, 3);
        qkv_proj_kernel<<<grid, 256>>>(x, Wq, Wk, Wv);
    }

    // 2) causal flash attention (writes g_ctx in [B,S,D])
    {
        const int smem_bytes = (64 * 64 + 2 * 64 * 65) * (int)sizeof(float); // 49664
        cudaFuncSetAttribute(attn_kernel,
                             cudaFuncAttributeMaxDynamicSharedMemorySize, smem_bytes);
        dim3 grid(S_ / QT, B_ * H_);
        attn_kernel<<<grid, 256, smem_bytes>>>();
    }

    // 3) output projection (writes d_out)
    {
        dim3 grid(D_ / BN, M_ / BM);
        oproj_kernel<<<grid, 256>>>(Wo, out);
    }
}

// round 9
// speedup vs baseline: 1.0040x; 1.0040x over previous
#include <cuda_runtime.h>
#include <cstdint>

// Problem constants
#define B_  4
#define S_  2048
#define D_  1024
#define H_  16
#define HD_ 64
#define M_  (B_*S_)   // 8192 rows

// Scratch (device globals — no allocation allowed)
__device__ float g_q[B_*H_*S_*HD_];   // [B,H,S,HD]
__device__ float g_k[B_*H_*S_*HD_];
__device__ float g_v[B_*H_*S_*HD_];
__device__ float g_ctx[(size_t)B_*S_*D_]; // [B,S,D]

// ---------------------------------------------------------------------------
// GEMM tile config: C[M,N] = A[M,K] * W[N,K]^T  (both K-major, row-major)
// 128x128 block tile, BK=16, 256 threads, 8x8 per-thread microtile with
// strided mapping (row = tm+16*i, col = tn+16*j) for conflict-free LDS.
// ---------------------------------------------------------------------------
#define BM 128
#define BN 128
#define BK 16

// Fused QKV projection: blockIdx.z in {0,1,2} selects (Wq->g_q, Wk->g_k, Wv->g_v).
// Epilogue permutes [m=b*S+s, n=h*HD+hd] -> [B,H,S,HD].
__global__ __launch_bounds__(256) void qkv_proj_kernel(
    const float* __restrict__ x,
    const float* __restrict__ Wq,
    const float* __restrict__ Wk,
    const float* __restrict__ Wv)
{
    const float* W   = (blockIdx.z == 0) ? Wq : (blockIdx.z == 1) ? Wk : Wv;
    float*       dst = (blockIdx.z == 0) ? g_q : (blockIdx.z == 1) ? g_k : g_v;

    __shared__ float As[BK][BM + 1];
    __shared__ float Bs[BK][BN + 1];

    const int tid = threadIdx.x;
    const int tm  = tid >> 4;   // 0..15
    const int tn  = tid & 15;   // 0..15
    const int m0  = blockIdx.y * BM;
    const int n0  = blockIdx.x * BN;

    float acc[8][8];
#pragma unroll
    for (int i = 0; i < 8; ++i)
#pragma unroll
        for (int j = 0; j < 8; ++j) acc[i][j] = 0.0f;

    for (int k0 = 0; k0 < D_; k0 += BK) {
#pragma unroll
        for (int l = 0; l < 2; ++l) {
            int idx = tid + l * 256;          // 0..511
            int r   = idx >> 2;               // 0..127
            int c4  = (idx & 3) << 2;         // 0,4,8,12
            float4 va = *(const float4*)(x + (size_t)(m0 + r) * D_ + k0 + c4);
            As[c4 + 0][r] = va.x; As[c4 + 1][r] = va.y;
            As[c4 + 2][r] = va.z; As[c4 + 3][r] = va.w;
            float4 vb = *(const float4*)(W + (size_t)(n0 + r) * D_ + k0 + c4);
            Bs[c4 + 0][r] = vb.x; Bs[c4 + 1][r] = vb.y;
            Bs[c4 + 2][r] = vb.z; Bs[c4 + 3][r] = vb.w;
        }
        __syncthreads();
#pragma unroll
        for (int k = 0; k < BK; ++k) {
            float a[8], b[8];
#pragma unroll
            for (int i = 0; i < 8; ++i) a[i] = As[k][tm + 16 * i];
#pragma unroll
            for (int j = 0; j < 8; ++j) b[j] = Bs[k][tn + 16 * j];
#pragma unroll
            for (int i = 0; i < 8; ++i)
#pragma unroll
                for (int j = 0; j < 8; ++j) acc[i][j] += a[i] * b[j];
        }
        __syncthreads();
    }

    // Permuted store: [B,H,S,HD]
#pragma unroll
    for (int i = 0; i < 8; ++i) {
        int m = m0 + tm + 16 * i;
        int b = m >> 11;            // / 2048
        int s = m & (S_ - 1);
#pragma unroll
        for (int j = 0; j < 8; ++j) {
            int n  = n0 + tn + 16 * j;
            int h  = n >> 6;
            int hd = n & 63;
            dst[(((size_t)(b * H_ + h)) * S_ + s) * HD_ + hd] = acc[i][j];
        }
    }
}

// Output projection: out[B,S,D] = ctx @ Wo^T (plain layout store)
__global__ __launch_bounds__(256) void oproj_kernel(
    const float* __restrict__ Wo,
    float* __restrict__ out)
{
    __shared__ float As[BK][BM + 1];
    __shared__ float Bs[BK][BN + 1];

    const int tid = threadIdx.x;
    const int tm  = tid >> 4;
    const int tn  = tid & 15;
    const int m0  = blockIdx.y * BM;
    const int n0  = blockIdx.x * BN;

    float acc[8][8];
#pragma unroll
    for (int i = 0; i < 8; ++i)
#pragma unroll
        for (int j = 0; j < 8; ++j) acc[i][j] = 0.0f;

    for (int k0 = 0; k0 < D_; k0 += BK) {
#pragma unroll
        for (int l = 0; l < 2; ++l) {
            int idx = tid + l * 256;
            int r   = idx >> 2;
            int c4  = (idx & 3) << 2;
            float4 va = *(const float4*)(g_ctx + (size_t)(m0 + r) * D_ + k0 + c4);
            As[c4 + 0][r] = va.x; As[c4 + 1][r] = va.y;
            As[c4 + 2][r] = va.z; As[c4 + 3][r] = va.w;
            float4 vb = *(const float4*)(Wo + (size_t)(n0 + r) * D_ + k0 + c4);
            Bs[c4 + 0][r] = vb.x; Bs[c4 + 1][r] = vb.y;
            Bs[c4 + 2][r] = vb.z; Bs[c4 + 3][r] = vb.w;
        }
        __syncthreads();
#pragma unroll
        for (int k = 0; k < BK; ++k) {
            float a[8], b[8];
#pragma unroll
            for (int i = 0; i < 8; ++i) a[i] = As[k][tm + 16 * i];
#pragma unroll
            for (int j = 0; j < 8; ++j) b[j] = Bs[k][tn + 16 * j];
#pragma unroll
            for (int i = 0; i < 8; ++i)
#pragma unroll
                for (int j = 0; j < 8; ++j) acc[i][j] += a[i] * b[j];
        }
        __syncthreads();
    }

#pragma unroll
    for (int i = 0; i < 8; ++i) {
        int m = m0 + tm + 16 * i;
#pragma unroll
        for (int j = 0; j < 8; ++j) {
            int n = n0 + tn + 16 * j;
            out[(size_t)m * D_ + n] = acc[i][j];
        }
    }
}

// ---------------------------------------------------------------------------
// Flash attention (fp32, causal). One block per (q-tile of 64 rows, b*h).
// 256 threads: ty=tid/16 owns rows {ty+16i}, tx=tid%16 owns cols {tx+16j}.
// smem: q_s[64][64], k_s[64][65] (reused for P), v_s[64][65]  -> 49664 B dyn.
// ---------------------------------------------------------------------------
#define QT 64
#define NEG_BIG (-1e30f)

__global__ __launch_bounds__(256) void attn_kernel()
{
    extern __shared__ float sm[];
    float* q_s = sm;                   // 64*64
    float* k_s = sm + 64 * 64;         // 64*65, reused as P
    float* v_s = k_s + 64 * 65;        // 64*65

    const int qt = blockIdx.x;         // 0..31
    const int bh = blockIdx.y;         // 0..63
    const float* Qg = g_q + (size_t)bh * S_ * HD_;
    const float* Kg = g_k + (size_t)bh * S_ * HD_;
    const float* Vg = g_v + (size_t)bh * S_ * HD_;

    const int tid = threadIdx.x;
    const int tx  = tid & 15;
    const int ty  = tid >> 4;

    // load Q tile (stride 64; reads are broadcast so no pad needed)
    for (int idx = tid; idx < QT * HD_; idx += 256) {
        int r = idx >> 6, c = idx & 63;
        q_s[r * 64 + c] = Qg[(size_t)(qt * QT + r) * HD_ + c];
    }

    float m_r[4], l_r[4], o[4][4];
#pragma unroll
    for (int i = 0; i < 4; ++i) {
        m_r[i] = NEG_BIG; l_r[i] = 0.0f;
#pragma unroll
        for (int j = 0; j < 4; ++j) o[i][j] = 0.0f;
    }

    for (int kt = 0; kt <= qt; ++kt) {
        __syncthreads();  // protect k_s (holds P of prev iter) + q_s on first iter
        for (int idx = tid; idx < QT * HD_; idx += 256) {
            int r = idx >> 6, c = idx & 63;
            k_s[r * 65 + c] = Kg[(size_t)(kt * QT + r) * HD_ + c];
            v_s[r * 65 + c] = Vg[(size_t)(kt * QT + r) * HD_ + c];
        }
        __syncthreads();

        // S = Q K^T  (each thread 4x4)
        float sv[4][4];
#pragma unroll
        for (int i = 0; i < 4; ++i)
#pragma unroll
            for (int j = 0; j < 4; ++j) sv[i][j] = 0.0f;

#pragma unroll 8
        for (int d = 0; d < HD_; ++d) {
            float qv[4], kv[4];
#pragma unroll
            for (int i = 0; i < 4; ++i) qv[i] = q_s[(ty + 16 * i) * 64 + d];
#pragma unroll
            for (int j = 0; j < 4; ++j) kv[j] = k_s[(tx + 16 * j) * 65 + d];
#pragma unroll
            for (int i = 0; i < 4; ++i)
#pragma unroll
                for (int j = 0; j < 4; ++j) sv[i][j] += qv[i] * kv[j];
        }

        const float sc = 0.125f;  // 1/sqrt(64)
        if (kt == qt) {
#pragma unroll
            for (int i = 0; i < 4; ++i)
#pragma unroll
                for (int j = 0; j < 4; ++j) {
                    int row = ty + 16 * i, col = tx + 16 * j;
                    sv[i][j] = (col > row) ? NEG_BIG : sv[i][j] * sc;
                }
        } else {
#pragma unroll
            for (int i = 0; i < 4; ++i)
#pragma unroll
                for (int j = 0; j < 4; ++j) sv[i][j] *= sc;
        }

        // row max across the 16 tx lanes (width-16 shfl segments)
        float mx[4];
#pragma unroll
        for (int i = 0; i < 4; ++i) {
            float v = fmaxf(fmaxf(sv[i][0], sv[i][1]), fmaxf(sv[i][2], sv[i][3]));
            mx[i] = v;
        }
#pragma unroll
        for (int off = 8; off; off >>= 1)
#pragma unroll
            for (int i = 0; i < 4; ++i)
                mx[i] = fmaxf(mx[i], __shfl_xor_sync(0xffffffffu, mx[i], off, 16));

        float al[4];
#pragma unroll
        for (int i = 0; i < 4; ++i) {
            float mn = fmaxf(m_r[i], mx[i]);
            al[i] = __expf(m_r[i] - mn);
            m_r[i] = mn;
        }

        float ps[4] = {0.f, 0.f, 0.f, 0.f};
#pragma unroll
        for (int i = 0; i < 4; ++i)
#pragma unroll
            for (int j = 0; j < 4; ++j) {
                float p = __expf(sv[i][j] - m_r[i]);
                sv[i][j] = p;
                ps[i] += p;
            }
#pragma unroll
        for (int off = 8; off; off >>= 1)
#pragma unroll
            for (int i = 0; i < 4; ++i)
                ps[i] += __shfl_xor_sync(0xffffffffu, ps[i], off, 16);

#pragma unroll
        for (int i = 0; i < 4; ++i) {
            l_r[i] = l_r[i] * al[i] + ps[i];
#pragma unroll
            for (int j = 0; j < 4; ++j) o[i][j] *= al[i];
        }

        __syncthreads();  // all threads done reading k_s -> safe to overwrite with P
#pragma unroll
        for (int i = 0; i < 4; ++i)
#pragma unroll
            for (int j = 0; j < 4; ++j)
                k_s[(ty + 16 * i) * 65 + (tx + 16 * j)] = sv[i][j];
        __syncthreads();

        // O += P V
#pragma unroll 8
        for (int k = 0; k < QT; ++k) {
            float pv[4], vv[4];
#pragma unroll
            for (int i = 0; i < 4; ++i) pv[i] = k_s[(ty + 16 * i) * 65 + k];
#pragma unroll
            for (int j = 0; j < 4; ++j) vv[j] = v_s[k * 65 + (tx + 16 * j)];
#pragma unroll
            for (int i = 0; i < 4; ++i)
#pragma unroll
                for (int j = 0; j < 4; ++j) o[i][j] += pv[i] * vv[j];
        }
    }

    // epilogue: ctx[b, s, h*64+c] = O / l
    const int b = bh >> 4;
    const int h = bh & 15;
#pragma unroll
    for (int i = 0; i < 4; ++i) {
        float inv = 1.0f / l_r[i];
        int srow = qt * QT + ty + 16 * i;
#pragma unroll
        for (int j = 0; j < 4; ++j) {
            int c = tx + 16 * j;
            g_ctx[((size_t)b * S_ + srow) * D_ + h * HD_ + c] = o[i][j] * inv;
        }
    }
}

// ---------------------------------------------------------------------------
// Launch
// ---------------------------------------------------------------------------
extern "C" void kernel_launch(void* const* d_in, const int* in_sizes, int n_in,
                              void* d_out, int out_size)
{
    const float* x  = (const float*)d_in[0];
    const float* Wq = (const float*)d_in[1];
    const float* Wk = (const float*)d_in[2];
    const float* Wv = (const float*)d_in[3];
    const float* Wo = (const float*)d_in[4];
    float* out = (float*)d_out;

    // 1) fused QKV projections (writes g_q/g_k/g_v in [B,H,S,HD])
    {
        dim3 grid(D_ / BN, M_ / BM, 3);
        qkv_proj_kernel<<<grid, 256>>>(x, Wq, Wk, Wv);
    }

    // 2) causal flash attention (writes g_ctx in [B,S,D])
    {
        const int smem_bytes = (64 * 64 + 2 * 64 * 65) * (int)sizeof(float); // 49664
        cudaFuncSetAttribute(attn_kernel,
                             cudaFuncAttributeMaxDynamicSharedMemorySize, smem_bytes);
        dim3 grid(S_ / QT, B_ * H_);
        attn_kernel<<<grid, 256, smem_bytes>>>();
    }

    // 3) output projection (writes d_out)
    {
        dim3 grid(D_ / BN, M_ / BM);
        oproj_kernel<<<grid, 256>>>(Wo, out);
    }
}